// round 4
// baseline (speedup 1.0000x reference)
#include <cuda_runtime.h>

// FFT-1024 per row via four-step 32x32 decomposition.
// One warp per row. Thread t holds column/row of the 32x32 view in registers.
// Exactly one shared-memory transpose per row (conflict-free, stride-33 split re/im).

__device__ constexpr int BR5[32] = {
     0,16, 8,24, 4,20,12,28, 2,18,10,26, 6,22,14,30,
     1,17, 9,25, 5,21,13,29, 3,19,11,27, 7,23,15,31};

// cos(k*pi/16), sin(k*pi/16), k = 0..15  (twiddle w = e^{-i k pi/16} = C - i*S)
__device__ constexpr float C16[16] = {
    1.0f,               0.980785280403230449f, 0.923879532511286756f, 0.831469612302545237f,
    0.707106781186547524f, 0.555570233019602225f, 0.382683432365089772f, 0.195090322016128268f,
    0.0f,              -0.195090322016128268f,-0.382683432365089772f,-0.555570233019602225f,
   -0.707106781186547524f,-0.831469612302545237f,-0.923879532511286756f,-0.980785280403230449f};
__device__ constexpr float S16[16] = {
    0.0f,               0.195090322016128268f, 0.382683432365089772f, 0.555570233019602225f,
    0.707106781186547524f, 0.831469612302545237f, 0.923879532511286756f, 0.980785280403230449f,
    1.0f,               0.980785280403230449f, 0.923879532511286756f, 0.831469612302545237f,
    0.707106781186547524f, 0.555570233019602225f, 0.382683432365089772f, 0.195090322016128268f};

__device__ __forceinline__ float2 cmul(float2 a, float2 b) {
    return make_float2(fmaf(a.x, b.x, -a.y * b.y),
                       fmaf(a.x, b.y,  a.y * b.x));
}

// In-place radix-2 DIF FFT of 32 points (forward, e^{-2pi i nk/32}).
// Natural-order input; on return v[i] = X[brev5(i)].
// All twiddles are compile-time immediates (full unroll).
__device__ __forceinline__ void fft32_dif(float2 v[32]) {
#pragma unroll
    for (int s = 0; s < 5; ++s) {
        const int half = 16 >> s;
#pragma unroll
        for (int b = 0; b < 32; b += (half << 1)) {
#pragma unroll
            for (int j = 0; j < half; ++j) {
                const int k = j << s;          // twiddle index into pi/16 tables
                float2 a = v[b + j];
                float2 c = v[b + j + half];
                v[b + j] = make_float2(a.x + c.x, a.y + c.y);
                const float dr = a.x - c.x;
                const float di = a.y - c.y;
                const float wr =  C16[k];
                const float wi = -S16[k];      // w = e^{-i k pi/16}
                v[b + j + half] = make_float2(fmaf(dr, wr, -di * wi),
                                              fmaf(dr, wi,  di * wr));
            }
        }
    }
}

#define WARPS_PER_BLOCK 4
#define THREADS_PER_BLOCK (WARPS_PER_BLOCK * 32)

__global__ void __launch_bounds__(THREADS_PER_BLOCK)
fft1024_batch_kernel(const float2* __restrict__ in, float2* __restrict__ out, int nrows)
{
    // Per-warp 32x33 transpose tiles, split re/im for conflict-free access.
    __shared__ float sre[WARPS_PER_BLOCK][32 * 33];
    __shared__ float sim[WARPS_PER_BLOCK][32 * 33];

    const int w = threadIdx.x >> 5;
    const int t = threadIdx.x & 31;
    const int row = blockIdx.x * WARPS_PER_BLOCK + w;
    if (row >= nrows) return;   // whole warp exits together

    const float2* __restrict__ src = in  + (size_t)row * 1024;
    float2* __restrict__       dst = out + (size_t)row * 1024;

    // ---- load: v[a] = x[32a + t]  (coalesced: lanes read consecutive float2) ----
    float2 v[32];
#pragma unroll
    for (int a = 0; a < 32; ++a) v[a] = src[a * 32 + t];

    // ---- step 1: FFT-32 over a (columns). v[i] = C[brev(i)][t] ----
    fft32_dif(v);

    // ---- transpose through smem (write lane-contiguous, read stride-33) ----
    float* re = sre[w];
    float* im = sim[w];
#pragma unroll
    for (int i = 0; i < 32; ++i) {
        const int c = BR5[i];
        re[c * 33 + t] = v[i].x;
        im[c * 33 + t] = v[i].y;
    }
    __syncwarp();
#pragma unroll
    for (int b = 0; b < 32; ++b) {
        v[b].x = re[t * 33 + b];
        v[b].y = im[t * 33 + b];
    }

    // ---- step 2: twiddle w1024^{t*b} via recurrence from one accurate sincospi ----
    float si, co;
    sincospif(-(float)t * (1.0f / 512.0f), &si, &co);   // e^{-2pi i t/1024}
    const float2 wt = make_float2(co, si);
    float2 cur = wt;
#pragma unroll
    for (int b = 1; b < 32; ++b) {
        v[b] = cmul(v[b], cur);
        cur = cmul(cur, wt);
    }

    // ---- step 3: FFT-32 over b (rows). u[i] = X[t + 32*brev(i)] ----
    fft32_dif(v);

    // ---- store: coalesced (lanes t consecutive at each unrolled i) ----
#pragma unroll
    for (int i = 0; i < 32; ++i) {
        dst[t + 32 * BR5[i]] = v[i];
    }
}

extern "C" void kernel_launch(void* const* d_in, const int* in_sizes, int n_in,
                              void* d_out, int out_size)
{
    const float2* in  = (const float2*)d_in[0];
    float2*       out = (float2*)d_out;
    const int nrows = in_sizes[0] / 2048;   // 2048 floats (1024 complex) per row
    const int grid = (nrows + WARPS_PER_BLOCK - 1) / WARPS_PER_BLOCK;
    fft1024_batch_kernel<<<grid, THREADS_PER_BLOCK>>>(in, out, nrows);
}

// round 5
// speedup vs baseline: 1.1341x; 1.1341x over previous
#include <cuda_runtime.h>

// Batched FFT-1024, four-step 32x32 decomposition, 64 threads (2 warps) per row.
// Each thread holds 16 complex values; the 32-point FFTs are done split-radix:
// per-thread register FFT-16 + one lane-pair combine stage via shfl_xor(.,1).
// One conflict-free shared-memory transpose per row (stride-33 split re/im).

__device__ constexpr int BR4[16] = {0,8,4,12,2,10,6,14,1,9,5,13,3,11,7,15};

// cos(k*pi/16), sin(k*pi/16), k = 0..15  (w32^k = C16[k] - i*S16[k])
__device__ constexpr float C16[16] = {
    1.0f,               0.980785280403230449f, 0.923879532511286756f, 0.831469612302545237f,
    0.707106781186547524f, 0.555570233019602225f, 0.382683432365089772f, 0.195090322016128268f,
    0.0f,              -0.195090322016128268f,-0.382683432365089772f,-0.555570233019602225f,
   -0.707106781186547524f,-0.831469612302545237f,-0.923879532511286756f,-0.980785280403230449f};
__device__ constexpr float S16[16] = {
    0.0f,               0.195090322016128268f, 0.382683432365089772f, 0.555570233019602225f,
    0.707106781186547524f, 0.831469612302545237f, 0.923879532511286756f, 0.980785280403230449f,
    1.0f,               0.980785280403230449f, 0.923879532511286756f, 0.831469612302545237f,
    0.707106781186547524f, 0.555570233019602225f, 0.382683432365089772f, 0.195090322016128268f};

__device__ __forceinline__ float2 cmul(float2 a, float2 b) {
    return make_float2(fmaf(a.x, b.x, -a.y * b.y),
                       fmaf(a.x, b.y,  a.y * b.x));
}

// In-place radix-2 DIF FFT-16 (forward). Natural-order input; v[i] = X[BR4[i]] on return.
// All twiddles are compile-time immediates (w16^m = w32^{2m} -> index 2m into C16/S16).
__device__ __forceinline__ void fft16_dif(float2 v[16]) {
#pragma unroll
    for (int s = 0; s < 4; ++s) {
        const int half = 8 >> s;
#pragma unroll
        for (int b = 0; b < 16; b += (half << 1)) {
#pragma unroll
            for (int j = 0; j < half; ++j) {
                const int k = j << (s + 1);     // twiddle index into pi/16 tables
                float2 a = v[b + j];
                float2 c = v[b + j + half];
                v[b + j] = make_float2(a.x + c.x, a.y + c.y);
                const float dr = a.x - c.x;
                const float di = a.y - c.y;
                if (k == 0) {
                    v[b + j + half] = make_float2(dr, di);
                } else if (k == 8) {            // w = -i : (dr + i di)*(-i) = (di, -dr)
                    v[b + j + half] = make_float2(di, -dr);
                } else {
                    const float wr =  C16[k];
                    const float wi = -S16[k];
                    v[b + j + half] = make_float2(fmaf(dr, wr, -di * wi),
                                                  fmaf(dr, wi,  di * wr));
                }
            }
        }
    }
}

#define ROWS_PER_BLOCK 2
#define THREADS_PER_BLOCK (ROWS_PER_BLOCK * 64)

__global__ void __launch_bounds__(THREADS_PER_BLOCK)
fft1024_batch_kernel(const float2* __restrict__ in, float2* __restrict__ out, int nrows)
{
    // Per-row 32x33 transpose tiles, split re/im (conflict-free stride-33).
    __shared__ float sre[ROWS_PER_BLOCK][32 * 33];
    __shared__ float sim[ROWS_PER_BLOCK][32 * 33];

    const int g  = threadIdx.x >> 6;     // row group within block
    const int l  = threadIdx.x & 63;     // lane within row group
    const int cr = l >> 1;               // column c (stage 1) == k1-row r (stage 2)
    const int h  = l & 1;                // split-radix half
    const float sg = h ? -1.0f : 1.0f;

    const int row = blockIdx.x * ROWS_PER_BLOCK + g;
    const bool active = (row < nrows);
    const int srow = active ? row : 0;   // safe source row for inactive tails

    const float2* __restrict__ src = in  + (size_t)srow * 1024;
    float2* __restrict__       dst = out + (size_t)srow * 1024;

    // ---- load: a = 2j + h, v[j] = x[32a + c] = x[64j + 32h + c] (2 full lines/warp) ----
    float2 v[16];
#pragma unroll
    for (int j = 0; j < 16; ++j) v[j] = src[64 * j + 32 * h + cr];

    // ---- stage 1: FFT-32 over a, DIT split-radix ----
    // per-thread FFT-16 of even (h=0) / odd (h=1) subsequence
    fft16_dif(v);

    float* re = sre[g];
    float* im = sim[g];
#pragma unroll
    for (int i = 0; i < 16; ++i) {
        const int k = BR4[i];
        // tw = (h==0) ? E[k] : w32^k * O[k]
        const float wr = h ? C16[k]  : 1.0f;
        const float wi = h ? -S16[k] : 0.0f;
        const float2 tw = cmul(v[i], make_float2(wr, wi));
        const float px = __shfl_xor_sync(0xffffffffu, tw.x, 1);
        const float py = __shfl_xor_sync(0xffffffffu, tw.y, 1);
        // h=0: E + wO = tw + p ; h=1: E - wO = p - tw
        const float rx = fmaf(sg, tw.x, px);
        const float ry = fmaf(sg, tw.y, py);
        const int k1 = k + 16 * h;                // X32 frequency index
        re[cr * 33 + k1] = rx;                    // smem[c][k1], conflict-free
        im[cr * 33 + k1] = ry;
    }

    __syncthreads();

    // ---- stage 2: twiddle w1024^{k1*n2}, then FFT-32 over n2, DIF split-radix ----
    // thread (r=cr, h) handles n2 = j + 16h, j = 0..15
    float si0, co0, si1, co1;
    sincospif(-(float)(cr * h) / 32.0f,  &si0, &co0);  // cur  = w1024^{16*r*h}
    sincospif(-(float)cr / 512.0f,       &si1, &co1);  // step = w1024^{r}
    float2 cur = make_float2(co0, si0);
    const float2 step = make_float2(co1, si1);

#pragma unroll
    for (int j = 0; j < 16; ++j) {
        const int n2 = j + 16 * h;
        float2 cv = make_float2(re[n2 * 33 + cr], im[n2 * 33 + cr]);  // conflict-free
        cv = cmul(cv, cur);                 // D[n2] = C[r][n2] * w1024^{r*n2}
        cur = cmul(cur, step);
        const float px = __shfl_xor_sync(0xffffffffu, cv.x, 1);
        const float py = __shfl_xor_sync(0xffffffffu, cv.y, 1);
        // h=0: low + high ; h=1: (low - high) * w32^j
        float2 g0 = make_float2(fmaf(sg, cv.x, px), fmaf(sg, cv.y, py));
        const float wr = h ? C16[j]  : 1.0f;
        const float wi = h ? -S16[j] : 0.0f;
        v[j] = cmul(g0, make_float2(wr, wi));
    }

    fft16_dif(v);

    // ---- store: k2 = 2*BR4[i] + h, out index = r + 32*k2... = cr + 32h + 64*BR4[i] ----
#pragma unroll
    for (int i = 0; i < 16; ++i) {
        if (active) dst[cr + 32 * h + 64 * BR4[i]] = v[i];
    }
}

extern "C" void kernel_launch(void* const* d_in, const int* in_sizes, int n_in,
                              void* d_out, int out_size)
{
    const float2* in  = (const float2*)d_in[0];
    float2*       out = (float2*)d_out;
    const int nrows = in_sizes[0] / 2048;   // 2048 floats (1024 complex) per row
    const int grid = (nrows + ROWS_PER_BLOCK - 1) / ROWS_PER_BLOCK;
    fft1024_batch_kernel<<<grid, THREADS_PER_BLOCK>>>(in, out, nrows);
}